// round 12
// baseline (speedup 1.0000x reference)
#include <cuda_runtime.h>
#include <cuda_bf16.h>
#include <cstdint>

// Problem dims
#define TT 8192
#define DIN 2048
#define DD 512
#define HH 512
#define AA 18
#define H3 1536

// GRU cluster config
#define CLN 16          // CTAs in the (single) cluster
#define GRUT 512        // threads per CTA

// Fallback (L2-ring) config
#define NCG 32
#define RGT 256
#define RING 4

typedef unsigned long long ull;

// ---------------- scratch (device globals; no allocation allowed) ----------------
__device__ float g_z1[(size_t)TT * DD];
__device__ float g_z2[(size_t)TT * DD];
__device__ float g_X[(size_t)TT * H3];
__device__ float g_seq[(size_t)TT * HH];
// L2 fallback ring: packed (value:f32 bits high 32 | tag:step low 32)
__device__ __align__(128) ull g_hp[RING][HH];

// ---------------- packed f32x2 helpers (sm_103a FFMA2) ----------------
__device__ __forceinline__ ull pk2(float lo, float hi) {
    ull r; asm("mov.b64 %0,{%1,%2};" : "=l"(r) : "f"(lo), "f"(hi)); return r;
}
__device__ __forceinline__ float2 upk2(ull v) {
    float2 r; asm("mov.b64 {%0,%1},%2;" : "=f"(r.x), "=f"(r.y) : "l"(v)); return r;
}
#define FMA2(d, a, b) asm("fma.rn.f32x2 %0,%1,%2,%0;" : "+l"(d) : "l"(a), "l"(b))

// ---------------- relaxed 64-bit global atomics (fallback path) ----------
__device__ __forceinline__ ull ld_rlx64(const ull* p) {
    ull v; asm volatile("ld.relaxed.gpu.global.b64 %0,[%1];" : "=l"(v) : "l"(p)); return v;
}
__device__ __forceinline__ void st_rlx64(ull* p, ull v) {
    asm volatile("st.relaxed.gpu.global.b64 [%0],%1;" :: "l"(p), "l"(v) : "memory");
}

// ---------------- cluster / mbarrier primitives ----------------
__device__ __forceinline__ uint32_t smem_u32(const void* p) {
    uint32_t a;
    asm("{ .reg .u64 t; cvta.to.shared.u64 t, %1; cvt.u32.u64 %0, t; }"
        : "=r"(a) : "l"(p));
    return a;
}
__device__ __forceinline__ uint32_t ctarank() {
    uint32_t r; asm("mov.u32 %0, %%cluster_ctarank;" : "=r"(r)); return r;
}
#define MAPA(out, addr, r) \
    asm("mapa.shared::cluster.u32 %0, %1, %2;" : "=r"(out) : "r"(addr), "r"(r))

#define MBAR_INIT(addr, count) \
    asm volatile("mbarrier.init.shared.b64 [%0], %1;" :: "r"(addr), "r"(count) : "memory")

#define ST_CLUSTER64(addr, v) \
    asm volatile("st.shared::cluster.u64 [%0], %1;" :: "r"(addr), "l"(v) : "memory")

#define MBAR_ARRIVE_REMOTE(addr) \
    asm volatile("mbarrier.arrive.release.cluster.shared::cluster.b64 _, [%0];" \
                 :: "r"(addr) : "memory")

#define WAITP(mbar, parity) do { \
    asm volatile("{\n\t.reg .pred P1;\n\t" \
        "WLOOP_%=:\n\t" \
        "mbarrier.try_wait.parity.acquire.cluster.shared::cta.b64 P1, [%0], %1, 0x989680;\n\t" \
        "@P1 bra WDONE_%=;\n\t" \
        "bra.uni WLOOP_%=;\n\t" \
        "WDONE_%=:\n\t}" \
        :: "r"(mbar), "r"(parity) : "memory"); } while (0)

#define CLUSTER_SYNC() do { \
    asm volatile("barrier.cluster.arrive.aligned;" ::: "memory"); \
    asm volatile("barrier.cluster.wait.aligned;" ::: "memory"); } while (0)

// ---------------- SGEMM (fp32, register blocked, f32x2 packed accum) ----------------
__device__ __forceinline__ void sgemm_body(
    const float* __restrict__ A, const float* __restrict__ B,
    const float* __restrict__ bias, float* __restrict__ C,
    int M, int N, int K, bool relu)
{
    constexpr int BM = 128, BN = 64, BK = 16, TM = 8, TN = 4;
    __shared__ __align__(16) float As[BK][BM];
    __shared__ __align__(16) float Bs[BK][BN];

    const int tid = threadIdx.x;
    const int tx = tid & 15;
    const int ty = tid >> 4;
    const int row0 = ty * TM;
    const int col0 = tx * TN;
    const int rowBase = blockIdx.y * BM;
    const int colBase = blockIdx.x * BN;

    ull acc2[TM / 2][TN];
#pragma unroll
    for (int i = 0; i < TM / 2; i++)
#pragma unroll
        for (int j = 0; j < TN; j++) acc2[i][j] = 0ull;

    for (int k0 = 0; k0 < K; k0 += BK) {
#pragma unroll
        for (int i = 0; i < 2; i++) {
            int idx = tid * 2 + i;
            int r = idx >> 2;
            int c4 = (idx & 3) * 4;
            float4 v = *(const float4*)(A + (size_t)(rowBase + r) * K + k0 + c4);
            As[c4 + 0][r] = v.x;
            As[c4 + 1][r] = v.y;
            As[c4 + 2][r] = v.z;
            As[c4 + 3][r] = v.w;
        }
        {
            int r = tid >> 4;
            int c = (tid & 15) * 4;
            *(float4*)&Bs[r][c] = *(const float4*)(B + (size_t)(k0 + r) * N + colBase + c);
        }
        __syncthreads();

#pragma unroll
        for (int kk = 0; kk < BK; kk++) {
            const ull* ap = (const ull*)&As[kk][row0];
            ull a01 = ap[0], a23 = ap[1], a45 = ap[2], a67 = ap[3];
            float4 b4 = *(float4*)&Bs[kk][col0];
            ull b0 = pk2(b4.x, b4.x), b1 = pk2(b4.y, b4.y);
            ull b2 = pk2(b4.z, b4.z), b3 = pk2(b4.w, b4.w);
            FMA2(acc2[0][0], a01, b0); FMA2(acc2[0][1], a01, b1);
            FMA2(acc2[0][2], a01, b2); FMA2(acc2[0][3], a01, b3);
            FMA2(acc2[1][0], a23, b0); FMA2(acc2[1][1], a23, b1);
            FMA2(acc2[1][2], a23, b2); FMA2(acc2[1][3], a23, b3);
            FMA2(acc2[2][0], a45, b0); FMA2(acc2[2][1], a45, b1);
            FMA2(acc2[2][2], a45, b2); FMA2(acc2[2][3], a45, b3);
            FMA2(acc2[3][0], a67, b0); FMA2(acc2[3][1], a67, b1);
            FMA2(acc2[3][2], a67, b2); FMA2(acc2[3][3], a67, b3);
        }
        __syncthreads();
    }

    float4 bv = *(const float4*)(bias + colBase + col0);
    float bb[TN] = {bv.x, bv.y, bv.z, bv.w};
#pragma unroll
    for (int i = 0; i < TM / 2; i++) {
        float2 c0 = upk2(acc2[i][0]);
        float2 c1 = upk2(acc2[i][1]);
        float2 c2 = upk2(acc2[i][2]);
        float2 c3 = upk2(acc2[i][3]);
        float lo[TN] = {c0.x + bb[0], c1.x + bb[1], c2.x + bb[2], c3.x + bb[3]};
        float hi[TN] = {c0.y + bb[0], c1.y + bb[1], c2.y + bb[2], c3.y + bb[3]};
        if (relu) {
#pragma unroll
            for (int j = 0; j < TN; j++) {
                lo[j] = fmaxf(lo[j], 0.f);
                hi[j] = fmaxf(hi[j], 0.f);
            }
        }
        float4 olo = {lo[0], lo[1], lo[2], lo[3]};
        float4 ohi = {hi[0], hi[1], hi[2], hi[3]};
        *(float4*)(C + (size_t)(rowBase + row0 + 2 * i) * N + colBase + col0) = olo;
        *(float4*)(C + (size_t)(rowBase + row0 + 2 * i + 1) * N + colBase + col0) = ohi;
    }
}

// gemm1 also initializes the fallback ring (harmless when cluster path is used)
__global__ __launch_bounds__(256) void k_gemm1(const float* __restrict__ x,
                                               const float* __restrict__ W1,
                                               const float* __restrict__ b1,
                                               const float* __restrict__ prev) {
    if (blockIdx.x == 0 && blockIdx.y == 0) {
        for (int i = threadIdx.x; i < HH; i += 256) {
            g_hp[0][i] = ((ull)__float_as_uint(prev[i]) << 32) | 0u;
            g_hp[1][i] = 0x0000000080000000ull;
            g_hp[2][i] = 0x0000000080000001ull;
            g_hp[3][i] = 0x0000000080000002ull;
        }
    }
    sgemm_body(x, W1, b1, g_z1, TT, DD, DIN, true);
}
__global__ __launch_bounds__(256) void k_gemm2(const float* __restrict__ W2,
                                               const float* __restrict__ b2) {
    sgemm_body(g_z1, W2, b2, g_z2, TT, DD, DD, true);
}
__global__ __launch_bounds__(256) void k_gemm3(const float* __restrict__ Wg,
                                               const float* __restrict__ bg) {
    sgemm_body(g_z2, Wg, bg, g_X, TT, H3, DD, false);
}

// ---------------- GRU A: ONE 16-CTA cluster, DSMEM push ----------
// 16 CTAs x 512 threads. CTA r owns h columns r*32..r*32+31. Per step:
// wait local mbar (h_t already pushed into LOCAL smem by all peers), matvec
// with register-resident weights, leaders stage 32 new values, __syncthreads,
// then lane p (p<16) stores the 32 values into peer p's buffer via
// st.shared::cluster and arrives (release) on peer p's mbarrier. No L2 in the
// recurrence. Double-buffered bufs+mbars; skew bounded by one step.
__global__ __launch_bounds__(GRUT, 1) void k_gru_cluster(
    const float* __restrict__ Ug,   // [512, 1536]
    const float* __restrict__ bg,   // [2, 1536]; row 1 = recurrent bias
    const float* __restrict__ prev) // [1, 512]
{
    __shared__ __align__(16) float buf[2][HH];
    __shared__ __align__(16) float xs[4][96];    // X pipeline, 2 steps ahead
    __shared__ __align__(16) float stage[32];
    __shared__ __align__(8)  ull   mbarS[2];

    const int tid = threadIdx.x;       // 0..511
    const int g = tid >> 4;            // 0..31  (column within CTA)
    const int s = tid & 15;            // 0..15  (interleaved k split)
    const uint32_t rank = ctarank();   // 0..15
    const int col = (int)rank * 32 + g;
    const bool leader = (s == 0);

    const uint32_t mb[2]   = { smem_u32(&mbarS[0]), smem_u32(&mbarS[1]) };
    const uint32_t bufa[2] = { smem_u32(&buf[0][0]), smem_u32(&buf[1][0]) };

    // Register-resident recurrent weights, packed f32x2, interleaved order
    ull w2[3][16];
#pragma unroll
    for (int q = 0; q < 3; q++) {
        const float* ugc = Ug + (size_t)q * HH + col;
#pragma unroll
        for (int j = 0; j < 16; j++) {
            int k0 = 2 * (s + 16 * j);
            w2[q][j] = pk2(ugc[(size_t)k0 * H3], ugc[(size_t)(k0 + 1) * H3]);
        }
    }
    float br0 = 0.f, br1 = 0.f, br2 = 0.f;
    if (leader) {
        br0 = bg[H3 + col];
        br1 = bg[H3 + HH + col];
        br2 = bg[H3 + 2 * HH + col];
    }

    if (tid == 0) {
        MBAR_INIT(mb[0], CLN);
        MBAR_INIT(mb[1], CLN);
    }
    buf[0][tid] = prev[tid];      // every CTA holds the full h_0
    if (tid >= 480) {             // preload X[0], X[1] (last warp)
        int l = tid - 480;
#pragma unroll
        for (int u = 0; u < 2; u++) {
            const float* xq = g_X + (size_t)u * H3 + rank * 32 + l;
            xs[u][l]      = __ldcs(xq);
            xs[u][32 + l] = __ldcs(xq + HH);
            xs[u][64 + l] = __ldcs(xq + 2 * HH);
        }
    }
    CLUSTER_SYNC();   // mbars + buf0 + xs valid cluster-wide

    int par0 = 0, par1 = 0;
    for (int t = 0; t < TT; t++) {
        if (t > 0) {
            if (t & 1) { WAITP(mb[1], par1); par1 ^= 1; }
            else       { WAITP(mb[0], par0); par0 ^= 1; }
        }
        const float* sh = buf[t & 1];

        // seq row t-1 (= h_t), by the designated CTA (1/16 balanced)
        if (t > 0 && (((t - 1) & 15) == (int)rank))
            __stcs(g_seq + (size_t)(t - 1) * HH + tid, sh[tid]);

        // X pipeline: load X[t+2] (last warp)
        if (tid >= 480) {
            int l = tid - 480;
            int u = (t + 2 < TT) ? (t + 2) : (TT - 1);
            const float* xq = g_X + (size_t)u * H3 + rank * 32 + l;
            float* xd = xs[(t + 2) & 3];
            xd[l]      = __ldcs(xq);
            xd[32 + l] = __ldcs(xq + HH);
            xd[64 + l] = __ldcs(xq + 2 * HH);
        }

        // matvec: conflict-free LDS.64, 48 FFMA2
        const ull* shu = (const ull*)sh;
        ull a0 = 0ull, a1 = 0ull, a2 = 0ull;
#pragma unroll
        for (int j = 0; j < 16; j++) {
            ull hp = shu[s + 16 * j];
            FMA2(a0, hp, w2[0][j]);
            FMA2(a1, hp, w2[1][j]);
            FMA2(a2, hp, w2[2][j]);
        }
        float2 f0 = upk2(a0), f1 = upk2(a1), f2 = upk2(a2);
        float s0 = f0.x + f0.y, s1 = f1.x + f1.y, s2 = f2.x + f2.y;
#pragma unroll
        for (int off = 8; off >= 1; off >>= 1) {
            s0 += __shfl_xor_sync(0xffffffffu, s0, off);
            s1 += __shfl_xor_sync(0xffffffffu, s1, off);
            s2 += __shfl_xor_sync(0xffffffffu, s2, off);
        }

        if (leader) {
            const float* xv = xs[t & 3];
            float hold = sh[col];
            float zt = 1.f / (1.f + __expf(-(xv[g] + s0 + br0)));
            float rt = 1.f / (1.f + __expf(-(xv[32 + g] + s1 + br1)));
            float hh = 1.f / (1.f + __expf(-(xv[64 + g] + rt * (s2 + br2))));
            stage[g] = zt * hold + (1.f - zt) * hh;
        }
        __syncthreads();   // stage done; also retires this step's buf reads

        // fanout: lane p pushes our 32 values to peer p, then arrives
        if (tid < CLN) {
            uint32_t remb;
            MAPA(remb, bufa[(t + 1) & 1], (uint32_t)tid);
            uint32_t dst = remb + rank * 128;          // our 32-col slice
            const ull* st64 = (const ull*)stage;
#pragma unroll
            for (int i = 0; i < 16; i++) {
                ull v = st64[i];                       // LDS broadcast
                ST_CLUSTER64(dst + i * 8, v);
            }
            uint32_t remm;
            MAPA(remm, mb[(t + 1) & 1], (uint32_t)tid);
            MBAR_ARRIVE_REMOTE(remm);                  // release-orders my stores
        }
    }

    // epilogue: h_TT arrived at mb[0]/buf[0]; write seq row TT-1
    WAITP(mb[0], par0);
    if ((((TT - 1) & 15)) == (int)rank)
        __stcs(g_seq + (size_t)(TT - 1) * HH + tid, buf[0][tid]);
    CLUSTER_SYNC();
}

// ---------------- GRU B (fallback): 32-CTA L2 data-as-flag ring (round-10) ----
__global__ __launch_bounds__(RGT, 1) void k_gru_ring(
    const float* __restrict__ Ug,
    const float* __restrict__ bg)
{
    const int tid = threadIdx.x;       // 0..255
    const int g = tid >> 4;
    const int s = tid & 15;
    const int col = blockIdx.x * 16 + g;
    const bool leader = (s == 0);

    __shared__ __align__(16) float sh_h[2][HH];

    ull w2[3][16];
#pragma unroll
    for (int q = 0; q < 3; q++) {
        const float* ugc = Ug + (size_t)q * HH + col;
#pragma unroll
        for (int j = 0; j < 16; j++) {
            int k0 = 2 * (s + 16 * j);
            w2[q][j] = pk2(ugc[(size_t)k0 * H3], ugc[(size_t)(k0 + 1) * H3]);
        }
    }
    float br0 = 0.f, br1 = 0.f, br2 = 0.f;
    if (leader) {
        br0 = bg[H3 + col];
        br1 = bg[H3 + HH + col];
        br2 = bg[H3 + 2 * HH + col];
    }

    const float* xp = g_X + col;
    float xa0 = 0.f, xa1 = 0.f, xa2 = 0.f;
    float xb0 = 0.f, xb1 = 0.f, xb2 = 0.f;
    if (leader) {
        xa0 = __ldcs(xp);  xa1 = __ldcs(xp + HH);  xa2 = __ldcs(xp + 2 * HH);
        xb0 = __ldcs(xp + H3); xb1 = __ldcs(xp + H3 + HH); xb2 = __ldcs(xp + H3 + 2 * HH);
    }
    xp += 2 * H3;

    ull v1 = ld_rlx64(g_hp[0] + tid);
    ull v2 = ld_rlx64(g_hp[0] + tid + 256);

    for (int t = 0; t < TT; t++) {
        const ull* bp = g_hp[t & (RING - 1)];
        while (((int)(unsigned)v1 != t) | ((int)(unsigned)v2 != t)) {
            if ((int)(unsigned)v1 != t) v1 = ld_rlx64(bp + tid);
            if ((int)(unsigned)v2 != t) v2 = ld_rlx64(bp + tid + 256);
        }
        float h1 = __uint_as_float((unsigned)(v1 >> 32));
        float h2v = __uint_as_float((unsigned)(v2 >> 32));
        float* sh = sh_h[t & 1];
        sh[tid] = h1;
        sh[tid + 256] = h2v;
        if (t > 0) {
            float* sq = g_seq + (size_t)(t - 1) * HH;
            __stcs(sq + tid, h1);
            __stcs(sq + tid + 256, h2v);
        }
        __syncthreads();

        float nc0 = 0.f, nc1 = 0.f, nc2 = 0.f;
        if (leader) {
            const float* xq = (t + 2 < TT) ? xp : xp - H3;
            nc0 = __ldcs(xq);
            nc1 = __ldcs(xq + HH);
            nc2 = __ldcs(xq + 2 * HH);
        }

        const ull* shu = (const ull*)sh;
        ull a0 = 0ull, a1 = 0ull, a2 = 0ull;
#pragma unroll
        for (int j = 0; j < 16; j++) {
            ull hp = shu[s + 16 * j];
            FMA2(a0, hp, w2[0][j]);
            FMA2(a1, hp, w2[1][j]);
            FMA2(a2, hp, w2[2][j]);
        }
        float2 f0 = upk2(a0), f1 = upk2(a1), f2 = upk2(a2);
        float s0 = f0.x + f0.y, s1 = f1.x + f1.y, s2 = f2.x + f2.y;
#pragma unroll
        for (int off = 8; off >= 1; off >>= 1) {
            s0 += __shfl_xor_sync(0xffffffffu, s0, off);
            s1 += __shfl_xor_sync(0xffffffffu, s1, off);
            s2 += __shfl_xor_sync(0xffffffffu, s2, off);
        }

        if (leader) {
            float hold = sh[col];
            float zt = 1.f / (1.f + __expf(-(xa0 + s0 + br0)));
            float rt = 1.f / (1.f + __expf(-(xa1 + s1 + br1)));
            float hh = 1.f / (1.f + __expf(-(xa2 + rt * (s2 + br2))));
            float hn = zt * hold + (1.f - zt) * hh;
            ull pv = ((ull)__float_as_uint(hn) << 32) | (unsigned)(t + 1);
            st_rlx64(&g_hp[(t + 1) & (RING - 1)][col], pv);
        }

        const ull* bn = g_hp[(t + 1) & (RING - 1)];
        v1 = ld_rlx64(bn + tid);
        v2 = ld_rlx64(bn + tid + 256);

        xa0 = xb0; xa1 = xb1; xa2 = xb2;
        xb0 = nc0; xb1 = nc1; xb2 = nc2;
        xp += H3;
    }

    {
        const ull* bp = g_hp[TT & (RING - 1)];
        while (((int)(unsigned)v1 != TT) | ((int)(unsigned)v2 != TT)) {
            if ((int)(unsigned)v1 != TT) v1 = ld_rlx64(bp + tid);
            if ((int)(unsigned)v2 != TT) v2 = ld_rlx64(bp + tid + 256);
        }
        float* sq = g_seq + (size_t)(TT - 1) * HH;
        __stcs(sq + tid, __uint_as_float((unsigned)(v1 >> 32)));
        __stcs(sq + tid + 256, __uint_as_float((unsigned)(v2 >> 32)));
    }
}

// ---------------- Heads: policy softmax + value + hT ----------------
__global__ __launch_bounds__(256) void k_head(
    const float* __restrict__ Wp, const float* __restrict__ bp,
    const float* __restrict__ Wv, const float* __restrict__ bv,
    float* __restrict__ policy, float* __restrict__ value, float* __restrict__ hT)
{
    __shared__ float sWp[HH * AA];   // 36 KB
    __shared__ float sWv[HH];
    __shared__ float sbp[AA];

    const int tid = threadIdx.x;
    for (int i = tid; i < HH * AA; i += 256) sWp[i] = Wp[i];
    for (int i = tid; i < HH; i += 256) sWv[i] = Wv[i];
    if (tid < AA) sbp[tid] = bp[tid];
    __syncthreads();

    if (blockIdx.x == 0) {
        for (int i = tid; i < HH; i += 256) hT[i] = g_seq[(size_t)(TT - 1) * HH + i];
    }

    const int warp = tid >> 5;
    const int lane = tid & 31;
    const int gwarp = blockIdx.x * 8 + warp;
    const int nwarps = gridDim.x * 8;
    const float bvv = bv[0];

    for (int row = gwarp; row < TT; row += nwarps) {
        float acc[AA + 1];
#pragma unroll
        for (int o = 0; o <= AA; o++) acc[o] = 0.f;

        const float* hrow = g_seq + (size_t)row * HH;
#pragma unroll 4
        for (int i = 0; i < HH / 32; i++) {
            int k = i * 32 + lane;
            float h = hrow[k];
            const float* wr = &sWp[k * AA];
#pragma unroll
            for (int o = 0; o < AA; o++) acc[o] = fmaf(h, wr[o], acc[o]);
            acc[AA] = fmaf(h, sWv[k], acc[AA]);
        }
#pragma unroll
        for (int off = 16; off >= 1; off >>= 1) {
#pragma unroll
            for (int o = 0; o <= AA; o++)
                acc[o] += __shfl_xor_sync(0xffffffffu, acc[o], off);
        }
        if (lane == 0) {
            float logits[AA];
            float mx = -1e30f;
#pragma unroll
            for (int o = 0; o < AA; o++) {
                logits[o] = acc[o] + sbp[o];
                mx = fmaxf(mx, logits[o]);
            }
            float sum = 0.f;
#pragma unroll
            for (int o = 0; o < AA; o++) {
                logits[o] = __expf(logits[o] - mx);
                sum += logits[o];
            }
            float inv = 1.f / sum;
            float* prow = policy + (size_t)row * AA;
#pragma unroll
            for (int o = 0; o < AA; o++) prow[o] = logits[o] * inv;
            value[row] = acc[AA] + bvv;
        }
    }
}

// ---------------- launch ----------------
extern "C" void kernel_launch(void* const* d_in, const int* in_sizes, int n_in,
                              void* d_out, int out_size) {
    const float* x    = (const float*)d_in[0];
    const float* prev = (const float*)d_in[1];
    const float* W1   = (const float*)d_in[2];
    const float* b1   = (const float*)d_in[3];
    const float* W2   = (const float*)d_in[4];
    const float* b2   = (const float*)d_in[5];
    const float* Wg   = (const float*)d_in[6];
    const float* Ug   = (const float*)d_in[7];
    const float* bg   = (const float*)d_in[8];
    const float* Wp   = (const float*)d_in[9];
    const float* bp   = (const float*)d_in[10];
    const float* Wv   = (const float*)d_in[11];
    const float* bv   = (const float*)d_in[12];

    float* out    = (float*)d_out;
    float* policy = out;                        // [T, A]
    float* value  = out + (size_t)TT * AA;      // [T, 1]
    float* hT     = out + (size_t)TT * AA + TT; // [1, H]

    dim3 blk(256);
    k_gemm1<<<dim3(DD / 64, TT / 128), blk>>>(x, W1, b1, prev);
    k_gemm2<<<dim3(DD / 64, TT / 128), blk>>>(W2, b2);
    k_gemm3<<<dim3(H3 / 64, TT / 128), blk>>>(Wg, bg);

    // GRU: try the 16-CTA cluster (DSMEM push); fall back to the proven
    // L2-ring kernel if the cluster launch is rejected.
    cudaFuncSetAttribute(k_gru_cluster,
                         cudaFuncAttributeNonPortableClusterSizeAllowed, 1);
    cudaLaunchConfig_t cfg = {};
    cfg.gridDim = dim3(CLN, 1, 1);
    cfg.blockDim = dim3(GRUT, 1, 1);
    cfg.dynamicSmemBytes = 0;
    cfg.stream = 0;
    cudaLaunchAttribute attrs[1];
    attrs[0].id = cudaLaunchAttributeClusterDimension;
    attrs[0].val.clusterDim.x = CLN;
    attrs[0].val.clusterDim.y = 1;
    attrs[0].val.clusterDim.z = 1;
    cfg.attrs = attrs;
    cfg.numAttrs = 1;
    cudaError_t e = cudaLaunchKernelEx(&cfg, k_gru_cluster, Ug, bg, prev);
    if (e != cudaSuccess) {
        (void)cudaGetLastError();   // clear sticky error
        k_gru_ring<<<NCG, RGT>>>(Ug, bg);
    }

    k_head<<<256, 256>>>(Wp, bp, Wv, bv, policy, value, hT);

    (void)in_sizes; (void)n_in; (void)out_size;
}

// round 16
// speedup vs baseline: 1.2757x; 1.2757x over previous
#include <cuda_runtime.h>
#include <cuda_bf16.h>
#include <cstdint>

// Problem dims
#define TT 8192
#define DIN 2048
#define DD 512
#define HH 512
#define AA 18
#define H3 1536

// GRU persistent-kernel config (L2 data-as-flag ring — proven round-10 design)
#define NCG 32
#define RGT 256
#define RING 4

typedef unsigned long long ull;

// ---------------- scratch (device globals; no allocation allowed) ----------------
__device__ float g_z1[(size_t)TT * DD];
__device__ float g_z2[(size_t)TT * DD];
__device__ float g_X[(size_t)TT * H3];
__device__ float g_seq[(size_t)TT * HH];
// h exchange ring: packed (value:f32 bits high 32 | tag:step low 32)
__device__ __align__(128) ull g_hp[RING][HH];

// ---------------- packed f32x2 helpers (sm_103a FFMA2) ----------------
__device__ __forceinline__ ull pk2(float lo, float hi) {
    ull r; asm("mov.b64 %0,{%1,%2};" : "=l"(r) : "f"(lo), "f"(hi)); return r;
}
__device__ __forceinline__ float2 upk2(ull v) {
    float2 r; asm("mov.b64 {%0,%1},%2;" : "=f"(r.x), "=f"(r.y) : "l"(v)); return r;
}
#define FMA2(d, a, b) asm("fma.rn.f32x2 %0,%1,%2,%0;" : "+l"(d) : "l"(a), "l"(b))

// ---------------- relaxed 64-bit global atomics (single-copy atomic) ----------
__device__ __forceinline__ ull ld_rlx64(const ull* p) {
    ull v; asm volatile("ld.relaxed.gpu.global.b64 %0,[%1];" : "=l"(v) : "l"(p)); return v;
}
__device__ __forceinline__ void st_rlx64(ull* p, ull v) {
    asm volatile("st.relaxed.gpu.global.b64 [%0],%1;" :: "l"(p), "l"(v) : "memory");
}

// ---------------- SGEMM (fp32, register blocked, f32x2 packed accum) ----------------
__device__ __forceinline__ void sgemm_body(
    const float* __restrict__ A, const float* __restrict__ B,
    const float* __restrict__ bias, float* __restrict__ C,
    int M, int N, int K, bool relu)
{
    constexpr int BM = 128, BN = 64, BK = 16, TM = 8, TN = 4;
    __shared__ __align__(16) float As[BK][BM];
    __shared__ __align__(16) float Bs[BK][BN];

    const int tid = threadIdx.x;
    const int tx = tid & 15;
    const int ty = tid >> 4;
    const int row0 = ty * TM;
    const int col0 = tx * TN;
    const int rowBase = blockIdx.y * BM;
    const int colBase = blockIdx.x * BN;

    ull acc2[TM / 2][TN];
#pragma unroll
    for (int i = 0; i < TM / 2; i++)
#pragma unroll
        for (int j = 0; j < TN; j++) acc2[i][j] = 0ull;

    for (int k0 = 0; k0 < K; k0 += BK) {
#pragma unroll
        for (int i = 0; i < 2; i++) {
            int idx = tid * 2 + i;
            int r = idx >> 2;
            int c4 = (idx & 3) * 4;
            float4 v = *(const float4*)(A + (size_t)(rowBase + r) * K + k0 + c4);
            As[c4 + 0][r] = v.x;
            As[c4 + 1][r] = v.y;
            As[c4 + 2][r] = v.z;
            As[c4 + 3][r] = v.w;
        }
        {
            int r = tid >> 4;
            int c = (tid & 15) * 4;
            *(float4*)&Bs[r][c] = *(const float4*)(B + (size_t)(k0 + r) * N + colBase + c);
        }
        __syncthreads();

#pragma unroll
        for (int kk = 0; kk < BK; kk++) {
            const ull* ap = (const ull*)&As[kk][row0];
            ull a01 = ap[0], a23 = ap[1], a45 = ap[2], a67 = ap[3];
            float4 b4 = *(float4*)&Bs[kk][col0];
            ull b0 = pk2(b4.x, b4.x), b1 = pk2(b4.y, b4.y);
            ull b2 = pk2(b4.z, b4.z), b3 = pk2(b4.w, b4.w);
            FMA2(acc2[0][0], a01, b0); FMA2(acc2[0][1], a01, b1);
            FMA2(acc2[0][2], a01, b2); FMA2(acc2[0][3], a01, b3);
            FMA2(acc2[1][0], a23, b0); FMA2(acc2[1][1], a23, b1);
            FMA2(acc2[1][2], a23, b2); FMA2(acc2[1][3], a23, b3);
            FMA2(acc2[2][0], a45, b0); FMA2(acc2[2][1], a45, b1);
            FMA2(acc2[2][2], a45, b2); FMA2(acc2[2][3], a45, b3);
            FMA2(acc2[3][0], a67, b0); FMA2(acc2[3][1], a67, b1);
            FMA2(acc2[3][2], a67, b2); FMA2(acc2[3][3], a67, b3);
        }
        __syncthreads();
    }

    float4 bv = *(const float4*)(bias + colBase + col0);
    float bb[TN] = {bv.x, bv.y, bv.z, bv.w};
#pragma unroll
    for (int i = 0; i < TM / 2; i++) {
        float2 c0 = upk2(acc2[i][0]);
        float2 c1 = upk2(acc2[i][1]);
        float2 c2 = upk2(acc2[i][2]);
        float2 c3 = upk2(acc2[i][3]);
        float lo[TN] = {c0.x + bb[0], c1.x + bb[1], c2.x + bb[2], c3.x + bb[3]};
        float hi[TN] = {c0.y + bb[0], c1.y + bb[1], c2.y + bb[2], c3.y + bb[3]};
        if (relu) {
#pragma unroll
            for (int j = 0; j < TN; j++) {
                lo[j] = fmaxf(lo[j], 0.f);
                hi[j] = fmaxf(hi[j], 0.f);
            }
        }
        float4 olo = {lo[0], lo[1], lo[2], lo[3]};
        float4 ohi = {hi[0], hi[1], hi[2], hi[3]};
        *(float4*)(C + (size_t)(rowBase + row0 + 2 * i) * N + colBase + col0) = olo;
        *(float4*)(C + (size_t)(rowBase + row0 + 2 * i + 1) * N + colBase + col0) = ohi;
    }
}

// gemm1 also performs the one-time ring init (rewrites ALL slots each replay,
// so graph replays always start from a clean tag state)
__global__ __launch_bounds__(256) void k_gemm1(const float* __restrict__ x,
                                               const float* __restrict__ W1,
                                               const float* __restrict__ b1,
                                               const float* __restrict__ prev) {
    if (blockIdx.x == 0 && blockIdx.y == 0) {
        for (int i = threadIdx.x; i < HH; i += 256) {
            g_hp[0][i] = ((ull)__float_as_uint(prev[i]) << 32) | 0u;
            g_hp[1][i] = 0x0000000080000000ull;
            g_hp[2][i] = 0x0000000080000001ull;
            g_hp[3][i] = 0x0000000080000002ull;
        }
    }
    sgemm_body(x, W1, b1, g_z1, TT, DD, DIN, true);
}
__global__ __launch_bounds__(256) void k_gemm2(const float* __restrict__ W2,
                                               const float* __restrict__ b2) {
    sgemm_body(g_z1, W2, b2, g_z2, TT, DD, DD, true);
}
__global__ __launch_bounds__(256) void k_gemm3(const float* __restrict__ Wg,
                                               const float* __restrict__ bg) {
    sgemm_body(g_z2, Wg, bg, g_X, TT, H3, DD, false);
}

// ---------------- GRU sequential scan (persistent, L2 data-as-flag ring) -------
// 32 CTAs x 256 threads. Column c of h_t lives in g_hp[t%4][c] as an 8-byte
// packed word (value<<32 | tag=t), written/read with relaxed gpu-scope atomics
// (single-copy atomic: the tag certifies the value; no fences, no counters).
// Lockstep dependency bounds CTA skew to one step -> the ring never clobbers
// a live slot. DSMEM cluster variant measured SLOWER (15.75 vs 13.01 ms, R12).
// g_seq stores issued after the FMA loop from registers (off the barrier path).
__global__ __launch_bounds__(RGT, 1) void k_gru(
    const float* __restrict__ Ug,   // [512, 1536]
    const float* __restrict__ bg)   // [2, 1536]; row 1 = recurrent bias
{
    const int tid = threadIdx.x;       // 0..255
    const int g = tid >> 4;            // 0..15  (column within CTA)
    const int s = tid & 15;            // 0..15  (interleaved k split)
    const int col = blockIdx.x * 16 + g;
    const bool leader = (s == 0);

    __shared__ __align__(16) float sh_h[2][HH];  // double-buffered staging

    // Register-resident recurrent weights, packed f32x2, interleaved order:
    // j-th pair for this thread is ull-pair p = s + 16*j -> k = 2p, 2p+1
    ull w2[3][16];
#pragma unroll
    for (int q = 0; q < 3; q++) {
        const float* ugc = Ug + (size_t)q * HH + col;
#pragma unroll
        for (int j = 0; j < 16; j++) {
            int k0 = 2 * (s + 16 * j);
            w2[q][j] = pk2(ugc[(size_t)k0 * H3], ugc[(size_t)(k0 + 1) * H3]);
        }
    }
    float br0 = 0.f, br1 = 0.f, br2 = 0.f;
    if (leader) {
        br0 = bg[H3 + col];
        br1 = bg[H3 + HH + col];
        br2 = bg[H3 + 2 * HH + col];
    }

    // X projections: triple-buffered (2 steps ahead)
    const float* xp = g_X + col;               // step t+2 load pointer
    float xa0 = 0.f, xa1 = 0.f, xa2 = 0.f;     // step t
    float xb0 = 0.f, xb1 = 0.f, xb2 = 0.f;     // step t+1
    if (leader) {
        xa0 = __ldcs(xp);  xa1 = __ldcs(xp + HH);  xa2 = __ldcs(xp + 2 * HH);
        xb0 = __ldcs(xp + H3); xb1 = __ldcs(xp + H3 + HH); xb2 = __ldcs(xp + H3 + 2 * HH);
    }
    xp += 2 * H3;

    // Early probes for step 0's slot
    ull v1 = ld_rlx64(g_hp[0] + tid);
    ull v2 = ld_rlx64(g_hp[0] + tid + 256);

    for (int t = 0; t < TT; t++) {
        // ---- stage h_t from ring slot t%4: joint poll until both tags == t ----
        const ull* bp = g_hp[t & (RING - 1)];
        while (((int)(unsigned)v1 != t) | ((int)(unsigned)v2 != t)) {
            if ((int)(unsigned)v1 != t) v1 = ld_rlx64(bp + tid);
            if ((int)(unsigned)v2 != t) v2 = ld_rlx64(bp + tid + 256);
        }
        float h1 = __uint_as_float((unsigned)(v1 >> 32));
        float h2v = __uint_as_float((unsigned)(v2 >> 32));
        float* sh = sh_h[t & 1];
        sh[tid] = h1;
        sh[tid + 256] = h2v;
        __syncthreads();   // staging complete; also retires prior-step smem reads

        // ---- prefetch X for step t+2 ----
        float nc0 = 0.f, nc1 = 0.f, nc2 = 0.f;
        if (leader) {
            const float* xq = (t + 2 < TT) ? xp : xp - H3;   // clamp at end
            nc0 = __ldcs(xq);
            nc1 = __ldcs(xq + HH);
            nc2 = __ldcs(xq + 2 * HH);
        }

        // ---- matvec: conflict-free LDS.64, 48 FFMA2 ----
        const ull* shu = (const ull*)sh;
        ull a0 = 0ull, a1 = 0ull, a2 = 0ull;
#pragma unroll
        for (int j = 0; j < 16; j++) {
            ull hp = shu[s + 16 * j];
            FMA2(a0, hp, w2[0][j]);
            FMA2(a1, hp, w2[1][j]);
            FMA2(a2, hp, w2[2][j]);
        }

        // seq row t-1 (= h_t) from registers — off the pre-barrier path,
        // overlapped with the reduce's latency
        if (t > 0) {
            float* sq = g_seq + (size_t)(t - 1) * HH;
            __stcs(sq + tid, h1);
            __stcs(sq + tid + 256, h2v);
        }

        float2 f0 = upk2(a0), f1 = upk2(a1), f2 = upk2(a2);
        float s0 = f0.x + f0.y, s1 = f1.x + f1.y, s2 = f2.x + f2.y;
#pragma unroll
        for (int off = 8; off >= 1; off >>= 1) {
            s0 += __shfl_xor_sync(0xffffffffu, s0, off);
            s1 += __shfl_xor_sync(0xffffffffu, s1, off);
            s2 += __shfl_xor_sync(0xffffffffu, s2, off);
        }

        if (leader) {
            float hold = sh[col];
            float zt = 1.f / (1.f + __expf(-(xa0 + s0 + br0)));
            float rt = 1.f / (1.f + __expf(-(xa1 + s1 + br1)));
            float hh = 1.f / (1.f + __expf(-(xa2 + rt * (s2 + br2))));
            float hn = zt * hold + (1.f - zt) * hh;
            // publish h_{t+1}: single relaxed 8B atomic store, tag certifies value
            ull pv = ((ull)__float_as_uint(hn) << 32) | (unsigned)(t + 1);
            st_rlx64(&g_hp[(t + 1) & (RING - 1)][col], pv);
        }

        // ---- early probes for step t+1's slot ----
        const ull* bn = g_hp[(t + 1) & (RING - 1)];
        v1 = ld_rlx64(bn + tid);
        v2 = ld_rlx64(bn + tid + 256);

        // rotate X buffers
        xa0 = xb0; xa1 = xb1; xa2 = xb2;
        xb0 = nc0; xb1 = nc1; xb2 = nc2;
        xp += H3;
    }

    // ---- epilogue: final h (tag TT) published but never staged; write row TT-1
    {
        const ull* bp = g_hp[TT & (RING - 1)];
        while (((int)(unsigned)v1 != TT) | ((int)(unsigned)v2 != TT)) {
            if ((int)(unsigned)v1 != TT) v1 = ld_rlx64(bp + tid);
            if ((int)(unsigned)v2 != TT) v2 = ld_rlx64(bp + tid + 256);
        }
        float* sq = g_seq + (size_t)(TT - 1) * HH;
        __stcs(sq + tid, __uint_as_float((unsigned)(v1 >> 32)));
        __stcs(sq + tid + 256, __uint_as_float((unsigned)(v2 >> 32)));
    }
}

// ---------------- Heads: policy softmax + value + hT ----------------
__global__ __launch_bounds__(256) void k_head(
    const float* __restrict__ Wp, const float* __restrict__ bp,
    const float* __restrict__ Wv, const float* __restrict__ bv,
    float* __restrict__ policy, float* __restrict__ value, float* __restrict__ hT)
{
    __shared__ float sWp[HH * AA];   // 36 KB
    __shared__ float sWv[HH];
    __shared__ float sbp[AA];

    const int tid = threadIdx.x;
    for (int i = tid; i < HH * AA; i += 256) sWp[i] = Wp[i];
    for (int i = tid; i < HH; i += 256) sWv[i] = Wv[i];
    if (tid < AA) sbp[tid] = bp[tid];
    __syncthreads();

    if (blockIdx.x == 0) {
        for (int i = tid; i < HH; i += 256) hT[i] = g_seq[(size_t)(TT - 1) * HH + i];
    }

    const int warp = tid >> 5;
    const int lane = tid & 31;
    const int gwarp = blockIdx.x * 8 + warp;
    const int nwarps = gridDim.x * 8;
    const float bvv = bv[0];

    for (int row = gwarp; row < TT; row += nwarps) {
        float acc[AA + 1];
#pragma unroll
        for (int o = 0; o <= AA; o++) acc[o] = 0.f;

        const float* hrow = g_seq + (size_t)row * HH;
#pragma unroll 4
        for (int i = 0; i < HH / 32; i++) {
            int k = i * 32 + lane;
            float h = hrow[k];
            const float* wr = &sWp[k * AA];
#pragma unroll
            for (int o = 0; o < AA; o++) acc[o] = fmaf(h, wr[o], acc[o]);
            acc[AA] = fmaf(h, sWv[k], acc[AA]);
        }
#pragma unroll
        for (int off = 16; off >= 1; off >>= 1) {
#pragma unroll
            for (int o = 0; o <= AA; o++)
                acc[o] += __shfl_xor_sync(0xffffffffu, acc[o], off);
        }
        if (lane == 0) {
            float logits[AA];
            float mx = -1e30f;
#pragma unroll
            for (int o = 0; o < AA; o++) {
                logits[o] = acc[o] + sbp[o];
                mx = fmaxf(mx, logits[o]);
            }
            float sum = 0.f;
#pragma unroll
            for (int o = 0; o < AA; o++) {
                logits[o] = __expf(logits[o] - mx);
                sum += logits[o];
            }
            float inv = 1.f / sum;
            float* prow = policy + (size_t)row * AA;
#pragma unroll
            for (int o = 0; o < AA; o++) prow[o] = logits[o] * inv;
            value[row] = acc[AA] + bvv;
        }
    }
}

// ---------------- launch ----------------
extern "C" void kernel_launch(void* const* d_in, const int* in_sizes, int n_in,
                              void* d_out, int out_size) {
    const float* x    = (const float*)d_in[0];
    const float* prev = (const float*)d_in[1];
    const float* W1   = (const float*)d_in[2];
    const float* b1   = (const float*)d_in[3];
    const float* W2   = (const float*)d_in[4];
    const float* b2   = (const float*)d_in[5];
    const float* Wg   = (const float*)d_in[6];
    const float* Ug   = (const float*)d_in[7];
    const float* bg   = (const float*)d_in[8];
    const float* Wp   = (const float*)d_in[9];
    const float* bp   = (const float*)d_in[10];
    const float* Wv   = (const float*)d_in[11];
    const float* bv   = (const float*)d_in[12];

    float* out    = (float*)d_out;
    float* policy = out;                        // [T, A]
    float* value  = out + (size_t)TT * AA;      // [T, 1]
    float* hT     = out + (size_t)TT * AA + TT; // [1, H]

    dim3 blk(256);
    k_gemm1<<<dim3(DD / 64, TT / 128), blk>>>(x, W1, b1, prev);
    k_gemm2<<<dim3(DD / 64, TT / 128), blk>>>(W2, b2);
    k_gemm3<<<dim3(H3 / 64, TT / 128), blk>>>(Wg, bg);

    k_gru<<<NCG, RGT>>>(Ug, bg);

    k_head<<<256, 256>>>(Wp, bp, Wv, bv, policy, value, hT);

    (void)in_sizes; (void)n_in; (void)out_size;
}